// round 3
// baseline (speedup 1.0000x reference)
#include <cuda_runtime.h>
#include <math.h>

#define NPART 4096
#define NC 16

#define R_ON2  (1.7f * 1.7f)       /* 2.89  */
#define R_C2   (4.0f)              /* 2.0^2 */
#define CUT_INV_DENOM (1.0f / ((R_C2 - R_ON2) * (R_C2 - R_ON2) * (R_C2 - R_ON2)))
#define ALPHA_F 2.8f

// scratch (no allocations allowed)
__device__ float  g_w[NPART * NC];   // w_i[d] = 0.5 * sum_c ct[c]*(E[c,d]+E[d,c])
__device__ float  g_mask[NPART];     // column mask: sum(ct_j) > 0
__device__ float4 g_pos4[NPART];     // x,y,z,radius
__device__ float  g_part[256];       // per-block partial sums (grid 4x64)

// XOR swizzle within 16-float groups (keeps index inside its group)
__device__ __forceinline__ int swz(int idx) { return idx ^ ((idx >> 4) & 15); }

// ---------------------------------------------------------------------------
// Kernel 1: per-particle contraction w_i = ct_i^T E_sym_i, mask, pos4 pack.
// 512 blocks x 256 threads, 8 particles per block. Two threads split each
// output's c-sum, combined with shfl_xor.
// ---------------------------------------------------------------------------
__global__ __launch_bounds__(256)
void prep_kernel(const float* __restrict__ pos,
                 const float* __restrict__ ct,
                 const float* __restrict__ E,
                 const float* __restrict__ rad) {
    __shared__ float sE[8 * 256];    // 8 KB, swizzled per particle
    __shared__ float sct[8 * NC];    // 512 B

    const int tid  = threadIdx.x;
    const int base = blockIdx.x * 8;

    // stage 2048 floats as 512 float4, scatter with swizzle
    const float4* __restrict__ E4 = (const float4*)(E + base * 256);
#pragma unroll
    for (int k = 0; k < 2; k++) {
        int q = tid + k * 256;       // float4 index 0..511
        float4 v = E4[q];
        int s = q * 4;
        sE[swz(s + 0)] = v.x;
        sE[swz(s + 1)] = v.y;
        sE[swz(s + 2)] = v.z;
        sE[swz(s + 3)] = v.w;
    }
    if (tid < 8 * NC) sct[tid] = ct[base * NC + tid];
    __syncthreads();

    const int out  = tid >> 1;       // 0..127 = (p,d)
    const int half = tid & 1;
    const int p = out >> 4;
    const int d = out & 15;

    float w = 0.0f;
#pragma unroll
    for (int cc = 0; cc < 8; cc++) {
        int c = half * 8 + cc;
        float ctc = sct[p * NC + c];
        w += ctc * (sE[p * 256 + swz(c * 16 + d)] + sE[p * 256 + swz(d * 16 + c)]);
    }
    w += __shfl_xor_sync(0xffffffffu, w, 1);

    const int i = base + p;
    if (half == 0) g_w[i * NC + d] = 0.5f * w;

    if (half == 0 && d == 0) {
        float s = 0.0f;
#pragma unroll
        for (int c = 0; c < NC; c++) s += sct[p * NC + c];
        g_mask[i] = (s > 0.0f) ? 1.0f : 0.0f;
        g_pos4[i] = make_float4(pos[3 * i], pos[3 * i + 1], pos[3 * i + 2], rad[i]);
    }
}

// ---------------------------------------------------------------------------
// Heavy path: rare (~0.05% of pairs). All j-side data comes from shared,
// i-side via 128-bit global loads (L1-resident after first touch).
// ---------------------------------------------------------------------------
__device__ __noinline__ float pair_energy(float r2, float ri, float rj, float mj,
                                          int ig, int jl,
                                          const float* __restrict__ ct,
                                          const float* __restrict__ sctj,
                                          const float* __restrict__ swj) {
    float dr = sqrtf(r2);
    float cut;
    if (r2 < R_ON2) {
        cut = 1.0f;
    } else {
        float t = R_C2 - r2;
        cut = t * t * (R_C2 + 2.0f * r2 - 3.0f * R_ON2) * CUT_INV_DENOM;
    }
    const float4* __restrict__ wi4 = (const float4*)(g_w + ig * NC);
    const float4* __restrict__ ci4 = (const float4*)(ct + ig * NC);
    const float* __restrict__ cj = sctj + jl * NC;
    const float* __restrict__ wj = swj + jl * NC;
    float dot = 0.0f;
#pragma unroll
    for (int q = 0; q < 4; q++) {
        float4 wi = wi4[q];
        float4 ci = ci4[q];
        dot += wi.x * cj[q * 4 + 0] + wj[q * 4 + 0] * ci.x;
        dot += wi.y * cj[q * 4 + 1] + wj[q * 4 + 1] * ci.y;
        dot += wi.z * cj[q * 4 + 2] + wj[q * 4 + 2] * ci.z;
        dot += wi.w * cj[q * 4 + 3] + wj[q * 4 + 3] * ci.w;
    }
    float er  = 0.5f * dot;
    float eps = (__fdividef(5.0f, 1.0f + __expf(-er)) + 0.3f) * mj;
    float u   = 1.0f - __expf(-ALPHA_F * (dr - (ri + rj)));
    return eps * (u * u - 1.0f) * cut;
}

// ---------------------------------------------------------------------------
// Kernel 2: O(N^2) screen. grid (4, 64), block 256. Each thread screens
// 4 i-particles against a 64-wide shared j-tile (pos+rad+mask+ct+w staged).
// ---------------------------------------------------------------------------
__global__ __launch_bounds__(256)
void pair_kernel(const float* __restrict__ ct) {
    __shared__ float4 spj[64];
    __shared__ float  smask[64];
    __shared__ float  sctj[64 * NC];   // 4 KB
    __shared__ float  swj[64 * NC];    // 4 KB

    const int tid   = threadIdx.x;
    const int jbase = blockIdx.y * 64;

    if (tid < 64) {
        int j = jbase + tid;
        spj[tid]   = g_pos4[j];
        smask[tid] = g_mask[j];
    }
    {
        const float4* __restrict__ ct4 = (const float4*)(ct + jbase * NC);
        const float4* __restrict__ w4  = (const float4*)(g_w + jbase * NC);
        ((float4*)sctj)[tid] = ct4[tid];
        ((float4*)swj)[tid]  = w4[tid];
    }
    __syncthreads();

    const int i0 = blockIdx.x * 1024 + tid;
    const float4 p0 = g_pos4[i0];
    const float4 p1 = g_pos4[i0 + 256];
    const float4 p2 = g_pos4[i0 + 512];
    const float4 p3 = g_pos4[i0 + 768];

    float acc0 = 0.0f, acc1 = 0.0f, acc2 = 0.0f, acc3 = 0.0f;

#pragma unroll 8
    for (int jj = 0; jj < 64; jj++) {
        float4 pj = spj[jj];
        float dx0 = p0.x - pj.x, dy0 = p0.y - pj.y, dz0 = p0.z - pj.z;
        float dx1 = p1.x - pj.x, dy1 = p1.y - pj.y, dz1 = p1.z - pj.z;
        float dx2 = p2.x - pj.x, dy2 = p2.y - pj.y, dz2 = p2.z - pj.z;
        float dx3 = p3.x - pj.x, dy3 = p3.y - pj.y, dz3 = p3.z - pj.z;
        float r20 = fmaf(dx0, dx0, fmaf(dy0, dy0, dz0 * dz0));
        float r21 = fmaf(dx1, dx1, fmaf(dy1, dy1, dz1 * dz1));
        float r22 = fmaf(dx2, dx2, fmaf(dy2, dy2, dz2 * dz2));
        float r23 = fmaf(dx3, dx3, fmaf(dy3, dy3, dz3 * dz3));
        if (r20 < R_C2 && r20 > 0.0f)
            acc0 += pair_energy(r20, p0.w, pj.w, smask[jj], i0,       jj, ct, sctj, swj);
        if (r21 < R_C2 && r21 > 0.0f)
            acc1 += pair_energy(r21, p1.w, pj.w, smask[jj], i0 + 256, jj, ct, sctj, swj);
        if (r22 < R_C2 && r22 > 0.0f)
            acc2 += pair_energy(r22, p2.w, pj.w, smask[jj], i0 + 512, jj, ct, sctj, swj);
        if (r23 < R_C2 && r23 > 0.0f)
            acc3 += pair_energy(r23, p3.w, pj.w, smask[jj], i0 + 768, jj, ct, sctj, swj);
    }

    // deterministic block tree-reduce
    __shared__ float red[256];
    red[tid] = (acc0 + acc1) + (acc2 + acc3);
    __syncthreads();
#pragma unroll
    for (int s = 128; s > 0; s >>= 1) {
        if (tid < s) red[tid] += red[tid + s];
        __syncthreads();
    }
    if (tid == 0) g_part[blockIdx.y * 4 + blockIdx.x] = red[0];
}

// ---------------------------------------------------------------------------
// Kernel 3: deterministic final reduction of 256 partials
// ---------------------------------------------------------------------------
__global__ void final_kernel(float* __restrict__ out) {
    __shared__ float red[256];
    int tid = threadIdx.x;
    red[tid] = g_part[tid];
    __syncthreads();
#pragma unroll
    for (int s = 128; s > 0; s >>= 1) {
        if (tid < s) red[tid] += red[tid + s];
        __syncthreads();
    }
    if (tid == 0) out[0] = 0.5f * red[0];
}

// ---------------------------------------------------------------------------
// Launch. Inputs (metadata order): position (N*3), celltype (N*16),
// epsilon (N*256), radius (N). Output: scalar float.
// ---------------------------------------------------------------------------
extern "C" void kernel_launch(void* const* d_in, const int* in_sizes, int n_in,
                              void* d_out, int out_size) {
    const float* pos = (const float*)d_in[0];
    const float* ct  = (const float*)d_in[1];
    const float* E   = (const float*)d_in[2];
    const float* rad = (const float*)d_in[3];
    float* out = (float*)d_out;

    prep_kernel<<<NPART / 8, 256>>>(pos, ct, E, rad);

    dim3 grid(4, 64);
    pair_kernel<<<grid, 256>>>(ct);

    final_kernel<<<1, 256>>>(out);
}

// round 4
// speedup vs baseline: 1.1780x; 1.1780x over previous
#include <cuda_runtime.h>
#include <math.h>

#define NPART 4096
#define NC 16

#define R_ON2  (1.7f * 1.7f)       /* 2.89  */
#define R_C2   (4.0f)              /* 2.0^2 */
#define CUT_INV_DENOM (1.0f / ((R_C2 - R_ON2) * (R_C2 - R_ON2) * (R_C2 - R_ON2)))
#define ALPHA_F 2.8f

// scratch (no allocations allowed)
__device__ float  g_w[NPART * NC];   // w_i[d] = 0.5 * sum_c ct[c]*(E[c,d]+E[d,c])
__device__ float  g_mask[NPART];     // column mask: sum(ct_j) > 0
__device__ float4 g_pos4[NPART];     // x,y,z,radius
__device__ float  g_part[512];       // per-block partial sums (grid 8x64)

// ---------------------------------------------------------------------------
// Kernel 1: per-particle contraction w_i = ct_i^T E_sym_i, mask, pos4 pack.
// One thread per (particle, dim). No smem, no sync: row d + ct live in
// registers (coalesced float4 loads across the particle's 16 lanes); the 16
// column reads are 64B-contiguous across lanes and L1-hit the row's lines.
// ---------------------------------------------------------------------------
__global__ __launch_bounds__(128)
void prep_kernel(const float* __restrict__ pos,
                 const float* __restrict__ ct,
                 const float* __restrict__ E,
                 const float* __restrict__ rad) {
    const int t = blockIdx.x * 128 + threadIdx.x;   // 0 .. 65535
    const int i = t >> 4;     // particle
    const int d = t & 15;     // output dim

    // celltype in registers
    const float4* __restrict__ ct4 = (const float4*)(ct + i * NC);
    float4 c0 = ct4[0], c1 = ct4[1], c2 = ct4[2], c3 = ct4[3];
    float sct[16] = {c0.x, c0.y, c0.z, c0.w, c1.x, c1.y, c1.z, c1.w,
                     c2.x, c2.y, c2.z, c2.w, c3.x, c3.y, c3.z, c3.w};

    // row d of E in registers
    const float4* __restrict__ Er4 = (const float4*)(E + i * 256 + d * NC);
    float4 r0 = Er4[0], r1 = Er4[1], r2 = Er4[2], r3 = Er4[3];
    float er[16] = {r0.x, r0.y, r0.z, r0.w, r1.x, r1.y, r1.z, r1.w,
                    r2.x, r2.y, r2.z, r2.w, r3.x, r3.y, r3.z, r3.w};

    // column d of E: 16 scalar loads, 64B-contiguous across lanes, L1-hot
    const float* __restrict__ Ec = E + i * 256 + d;
    float w = 0.0f;
#pragma unroll
    for (int c = 0; c < 16; c++) {
        w = fmaf(sct[c], er[c] + __ldg(Ec + c * 16), w);
    }
    g_w[t] = 0.5f * w;

    if (d == 0) {
        float s = 0.0f;
#pragma unroll
        for (int c = 0; c < 16; c++) s += sct[c];
        g_mask[i] = (s > 0.0f) ? 1.0f : 0.0f;
        g_pos4[i] = make_float4(pos[3 * i], pos[3 * i + 1], pos[3 * i + 2], rad[i]);
    }
}

// ---------------------------------------------------------------------------
// Heavy path: rare (~0.05% of pairs). j-side data from shared, i-side 128-bit
// global loads (L2-resident). Inlined; MUFU transcendentals.
// ---------------------------------------------------------------------------
__device__ __forceinline__ float pair_energy(float r2, float ri, float rj, float mj,
                                             int ig, int jl,
                                             const float* __restrict__ ct,
                                             const float* __restrict__ sctj,
                                             const float* __restrict__ swj) {
    float dr = sqrtf(r2);
    float cut;
    if (r2 < R_ON2) {
        cut = 1.0f;
    } else {
        float t = R_C2 - r2;
        cut = t * t * (R_C2 + 2.0f * r2 - 3.0f * R_ON2) * CUT_INV_DENOM;
    }
    const float4* __restrict__ wi4 = (const float4*)(g_w + ig * NC);
    const float4* __restrict__ ci4 = (const float4*)(ct + ig * NC);
    const float* __restrict__ cj = sctj + jl * NC;
    const float* __restrict__ wj = swj + jl * NC;
    float dot = 0.0f;
#pragma unroll
    for (int q = 0; q < 4; q++) {
        float4 wi = wi4[q];
        float4 ci = ci4[q];
        dot = fmaf(wi.x, cj[q * 4 + 0], dot); dot = fmaf(wj[q * 4 + 0], ci.x, dot);
        dot = fmaf(wi.y, cj[q * 4 + 1], dot); dot = fmaf(wj[q * 4 + 1], ci.y, dot);
        dot = fmaf(wi.z, cj[q * 4 + 2], dot); dot = fmaf(wj[q * 4 + 2], ci.z, dot);
        dot = fmaf(wi.w, cj[q * 4 + 3], dot); dot = fmaf(wj[q * 4 + 3], ci.w, dot);
    }
    float er  = 0.5f * dot;
    float eps = (__fdividef(5.0f, 1.0f + __expf(-er)) + 0.3f) * mj;
    float u   = 1.0f - __expf(-ALPHA_F * (dr - (ri + rj)));
    return eps * (u * u - 1.0f) * cut;
}

// ---------------------------------------------------------------------------
// Kernel 2: O(N^2) screen. grid (8, 64), block 256 -> 512 blocks (fine-grain
// wave balance). Each thread screens 2 i-particles against a 64-wide shared
// j-tile (pos+rad+mask+ct+w staged in smem).
// ---------------------------------------------------------------------------
__global__ __launch_bounds__(256)
void pair_kernel(const float* __restrict__ ct) {
    __shared__ float4 spj[64];
    __shared__ float  smask[64];
    __shared__ float  sctj[64 * NC];   // 4 KB
    __shared__ float  swj[64 * NC];    // 4 KB

    const int tid   = threadIdx.x;
    const int jbase = blockIdx.y * 64;

    if (tid < 64) {
        int j = jbase + tid;
        spj[tid]   = g_pos4[j];
        smask[tid] = g_mask[j];
    }
    {
        const float4* __restrict__ ct4 = (const float4*)(ct + jbase * NC);
        const float4* __restrict__ w4  = (const float4*)(g_w + jbase * NC);
        ((float4*)sctj)[tid] = ct4[tid];
        ((float4*)swj)[tid]  = w4[tid];
    }
    __syncthreads();

    const int i0 = blockIdx.x * 512 + tid;
    const int i1 = i0 + 256;
    const float4 p0 = g_pos4[i0];
    const float4 p1 = g_pos4[i1];

    float acc0 = 0.0f, acc1 = 0.0f;

#pragma unroll 8
    for (int jj = 0; jj < 64; jj++) {
        float4 pj = spj[jj];
        float dx0 = p0.x - pj.x, dy0 = p0.y - pj.y, dz0 = p0.z - pj.z;
        float dx1 = p1.x - pj.x, dy1 = p1.y - pj.y, dz1 = p1.z - pj.z;
        float r20 = fmaf(dx0, dx0, fmaf(dy0, dy0, dz0 * dz0));
        float r21 = fmaf(dx1, dx1, fmaf(dy1, dy1, dz1 * dz1));
        if (r20 < R_C2 && r20 > 0.0f)
            acc0 += pair_energy(r20, p0.w, pj.w, smask[jj], i0, jj, ct, sctj, swj);
        if (r21 < R_C2 && r21 > 0.0f)
            acc1 += pair_energy(r21, p1.w, pj.w, smask[jj], i1, jj, ct, sctj, swj);
    }

    // deterministic block tree-reduce
    __shared__ float red[256];
    red[tid] = acc0 + acc1;
    __syncthreads();
#pragma unroll
    for (int s = 128; s > 0; s >>= 1) {
        if (tid < s) red[tid] += red[tid + s];
        __syncthreads();
    }
    if (tid == 0) g_part[blockIdx.y * 8 + blockIdx.x] = red[0];
}

// ---------------------------------------------------------------------------
// Kernel 3: deterministic final reduction of 512 partials
// ---------------------------------------------------------------------------
__global__ void final_kernel(float* __restrict__ out) {
    __shared__ float red[256];
    int tid = threadIdx.x;
    red[tid] = g_part[tid] + g_part[tid + 256];
    __syncthreads();
#pragma unroll
    for (int s = 128; s > 0; s >>= 1) {
        if (tid < s) red[tid] += red[tid + s];
        __syncthreads();
    }
    if (tid == 0) out[0] = 0.5f * red[0];
}

// ---------------------------------------------------------------------------
// Launch. Inputs (metadata order): position (N*3), celltype (N*16),
// epsilon (N*256), radius (N). Output: scalar float.
// ---------------------------------------------------------------------------
extern "C" void kernel_launch(void* const* d_in, const int* in_sizes, int n_in,
                              void* d_out, int out_size) {
    const float* pos = (const float*)d_in[0];
    const float* ct  = (const float*)d_in[1];
    const float* E   = (const float*)d_in[2];
    const float* rad = (const float*)d_in[3];
    float* out = (float*)d_out;

    prep_kernel<<<NPART * NC / 128, 128>>>(pos, ct, E, rad);

    dim3 grid(8, 64);
    pair_kernel<<<grid, 256>>>(ct);

    final_kernel<<<1, 256>>>(out);
}

// round 5
// speedup vs baseline: 1.2275x; 1.0420x over previous
#include <cuda_runtime.h>
#include <math.h>

#define NPART 4096
#define NC 16

#define R_ON2  (1.7f * 1.7f)       /* 2.89  */
#define R_C2   (4.0f)              /* 2.0^2 */
#define CUT_INV_DENOM (1.0f / ((R_C2 - R_ON2) * (R_C2 - R_ON2) * (R_C2 - R_ON2)))
#define ALPHA_F 2.8f

#define GRID_X 8
#define GRID_Y 64
#define NBLK (GRID_X * GRID_Y)

// scratch (no allocations allowed)
__device__ float  g_w[NPART * NC];   // w_i[d] = 0.5 * sum_c ct[c]*(E[c,d]+E[d,c])
__device__ float  g_mask[NPART];     // column mask: sum(ct_j) > 0
__device__ float4 g_pos4[NPART];     // x,y,z,radius
__device__ float  g_part[NBLK];      // per-block partial sums
__device__ unsigned int g_count;     // last-block counter

// ---------------------------------------------------------------------------
// Kernel 1: per-particle contraction w_i = ct_i^T E_sym_i, mask, pos4 pack.
// One thread per (particle, dim). No smem, no sync.
// ---------------------------------------------------------------------------
__global__ __launch_bounds__(128)
void prep_kernel(const float* __restrict__ pos,
                 const float* __restrict__ ct,
                 const float* __restrict__ E,
                 const float* __restrict__ rad) {
    const int t = blockIdx.x * 128 + threadIdx.x;   // 0 .. 65535
    const int i = t >> 4;     // particle
    const int d = t & 15;     // output dim

    if (t == 0) g_count = 0;  // reset fused-reduction counter each launch

    // celltype in registers
    const float4* __restrict__ ct4 = (const float4*)(ct + i * NC);
    float4 c0 = ct4[0], c1 = ct4[1], c2 = ct4[2], c3 = ct4[3];
    float sct[16] = {c0.x, c0.y, c0.z, c0.w, c1.x, c1.y, c1.z, c1.w,
                     c2.x, c2.y, c2.z, c2.w, c3.x, c3.y, c3.z, c3.w};

    // row d of E in registers
    const float4* __restrict__ Er4 = (const float4*)(E + i * 256 + d * NC);
    float4 r0 = Er4[0], r1 = Er4[1], r2 = Er4[2], r3 = Er4[3];
    float er[16] = {r0.x, r0.y, r0.z, r0.w, r1.x, r1.y, r1.z, r1.w,
                    r2.x, r2.y, r2.z, r2.w, r3.x, r3.y, r3.z, r3.w};

    // column d of E: 16 scalar loads, 64B-contiguous across lanes, L1-hot
    const float* __restrict__ Ec = E + i * 256 + d;
    float w = 0.0f;
#pragma unroll
    for (int c = 0; c < 16; c++) {
        w = fmaf(sct[c], er[c] + __ldg(Ec + c * 16), w);
    }
    g_w[t] = 0.5f * w;

    if (d == 0) {
        float s = 0.0f;
#pragma unroll
        for (int c = 0; c < 16; c++) s += sct[c];
        g_mask[i] = (s > 0.0f) ? 1.0f : 0.0f;
        g_pos4[i] = make_float4(pos[3 * i], pos[3 * i + 1], pos[3 * i + 2], rad[i]);
    }
}

// ---------------------------------------------------------------------------
// Heavy path (rare). Returns base_ij * (mask_i + mask_j); caller's final sum
// is scaled by 0.5 (unordered-pair form of the reference's 0.5*sum_ordered).
// ---------------------------------------------------------------------------
__device__ __forceinline__ float pair_energy(float r2, float ri, float rj,
                                             float mi, float mj,
                                             int ig, int jl,
                                             const float* __restrict__ ct,
                                             const float* __restrict__ sctj,
                                             const float* __restrict__ swj) {
    float dr = sqrtf(r2);
    float t  = R_C2 - r2;
    float poly = t * t * (R_C2 + 2.0f * r2 - 3.0f * R_ON2) * CUT_INV_DENOM;
    float cut  = (r2 < R_ON2) ? 1.0f : poly;           // branchless select
    const float4* __restrict__ wi4 = (const float4*)(g_w + ig * NC);
    const float4* __restrict__ ci4 = (const float4*)(ct + ig * NC);
    const float* __restrict__ cj = sctj + jl * NC;
    const float* __restrict__ wj = swj + jl * NC;
    float dot = 0.0f;
#pragma unroll
    for (int q = 0; q < 4; q++) {
        float4 wi = wi4[q];
        float4 ci = ci4[q];
        dot = fmaf(wi.x, cj[q * 4 + 0], dot); dot = fmaf(wj[q * 4 + 0], ci.x, dot);
        dot = fmaf(wi.y, cj[q * 4 + 1], dot); dot = fmaf(wj[q * 4 + 1], ci.y, dot);
        dot = fmaf(wi.z, cj[q * 4 + 2], dot); dot = fmaf(wj[q * 4 + 2], ci.z, dot);
        dot = fmaf(wi.w, cj[q * 4 + 3], dot); dot = fmaf(wj[q * 4 + 3], ci.w, dot);
    }
    float er  = 0.5f * dot;
    float eps = __fdividef(5.0f, 1.0f + __expf(-er)) + 0.3f;
    float u   = 1.0f - __expf(-ALPHA_F * (dr - (ri + rj)));
    return eps * (u * u - 1.0f) * cut * (mi + mj);
}

// ---------------------------------------------------------------------------
// Kernel 2: upper-triangle screen + fused final reduction.
// grid (8, 64), block 256. i-range = [bx*512, bx*512+512) (2 regs/thread),
// j-tile = [by*64, by*64+64). Blocks with j-tile entirely <= i-range skip;
// entirely above run predicate-light full loop; overlap does per-pair j>i.
// ---------------------------------------------------------------------------
__global__ __launch_bounds__(256)
void pair_kernel(const float* __restrict__ ct, float* __restrict__ out) {
    __shared__ float4 spj[64];
    __shared__ float  smask[64];
    __shared__ float  sctj[64 * NC];   // 4 KB
    __shared__ float  swj[64 * NC];    // 4 KB
    __shared__ float  red[256];

    const int tid   = threadIdx.x;
    const int bx    = blockIdx.x;
    const int by    = blockIdx.y;
    const int jbase = by * 64;
    const int ibase = bx * 512;

    const bool skip = (jbase + 64 <= ibase);        // all j < all i
    const bool full = (jbase >= ibase + 512);       // all j > all i

    float acc = 0.0f;

    if (!skip) {
        if (tid < 64) {
            int j = jbase + tid;
            spj[tid]   = g_pos4[j];
            smask[tid] = g_mask[j];
        }
        {
            const float4* __restrict__ ct4 = (const float4*)(ct + jbase * NC);
            const float4* __restrict__ w4  = (const float4*)(g_w + jbase * NC);
            ((float4*)sctj)[tid] = ct4[tid];
            ((float4*)swj)[tid]  = w4[tid];
        }
        __syncthreads();

        const int i0 = ibase + tid;
        const int i1 = i0 + 256;
        const float4 p0 = g_pos4[i0];
        const float4 p1 = g_pos4[i1];
        const float m0 = g_mask[i0];
        const float m1 = g_mask[i1];

        if (full) {
#pragma unroll 8
            for (int jj = 0; jj < 64; jj++) {
                float4 pj = spj[jj];
                float dx0 = p0.x - pj.x, dy0 = p0.y - pj.y, dz0 = p0.z - pj.z;
                float dx1 = p1.x - pj.x, dy1 = p1.y - pj.y, dz1 = p1.z - pj.z;
                float r20 = fmaf(dx0, dx0, fmaf(dy0, dy0, dz0 * dz0));
                float r21 = fmaf(dx1, dx1, fmaf(dy1, dy1, dz1 * dz1));
                if (r20 < R_C2)
                    acc += pair_energy(r20, p0.w, pj.w, m0, smask[jj], i0, jj, ct, sctj, swj);
                if (r21 < R_C2)
                    acc += pair_energy(r21, p1.w, pj.w, m1, smask[jj], i1, jj, ct, sctj, swj);
            }
        } else {
            // diagonal-overlap block: per-pair j > i
#pragma unroll 8
            for (int jj = 0; jj < 64; jj++) {
                float4 pj = spj[jj];
                int jg = jbase + jj;
                float dx0 = p0.x - pj.x, dy0 = p0.y - pj.y, dz0 = p0.z - pj.z;
                float dx1 = p1.x - pj.x, dy1 = p1.y - pj.y, dz1 = p1.z - pj.z;
                float r20 = fmaf(dx0, dx0, fmaf(dy0, dy0, dz0 * dz0));
                float r21 = fmaf(dx1, dx1, fmaf(dy1, dy1, dz1 * dz1));
                if (r20 < R_C2 && jg > i0)
                    acc += pair_energy(r20, p0.w, pj.w, m0, smask[jj], i0, jj, ct, sctj, swj);
                if (r21 < R_C2 && jg > i1)
                    acc += pair_energy(r21, p1.w, pj.w, m1, smask[jj], i1, jj, ct, sctj, swj);
            }
        }
        __syncthreads();   // smem reuse barrier before reduction
    }

    // deterministic block tree-reduce
    red[tid] = acc;
    __syncthreads();
#pragma unroll
    for (int s = 128; s > 0; s >>= 1) {
        if (tid < s) red[tid] += red[tid + s];
        __syncthreads();
    }

    const int bid = by * GRID_X + bx;
    __shared__ bool is_last;
    if (tid == 0) {
        g_part[bid] = red[0];
        __threadfence();
        unsigned int done = atomicAdd(&g_count, 1u);
        is_last = (done == NBLK - 1);
    }
    __syncthreads();

    // last block performs the (deterministic-order) final reduction
    if (is_last) {
        red[tid] = g_part[tid] + g_part[tid + 256];
        __syncthreads();
#pragma unroll
        for (int s = 128; s > 0; s >>= 1) {
            if (tid < s) red[tid] += red[tid + s];
            __syncthreads();
        }
        if (tid == 0) out[0] = 0.5f * red[0];
    }
}

// ---------------------------------------------------------------------------
// Launch. Inputs (metadata order): position (N*3), celltype (N*16),
// epsilon (N*256), radius (N). Output: scalar float.
// ---------------------------------------------------------------------------
extern "C" void kernel_launch(void* const* d_in, const int* in_sizes, int n_in,
                              void* d_out, int out_size) {
    const float* pos = (const float*)d_in[0];
    const float* ct  = (const float*)d_in[1];
    const float* E   = (const float*)d_in[2];
    const float* rad = (const float*)d_in[3];
    float* out = (float*)d_out;

    prep_kernel<<<NPART * NC / 128, 128>>>(pos, ct, E, rad);

    dim3 grid(GRID_X, GRID_Y);
    pair_kernel<<<grid, 256>>>(ct, out);
}